// round 15
// baseline (speedup 1.0000x reference)
#include <cuda_runtime.h>
#include <cstdint>

// Problem constants
#define NB   64
#define CC   256
#define HH   28
#define WW   28
#define PIX  (HH*WW)                 // 784
#define NPIX (NB*PIX)                // 50176
#define TOT  (NB*CC*PIX)             // 12,845,056
#define CW   8                       // 256 channels / 32 bits
#define OCCH 32                      // output channels per block
#define NCH  (CC/OCCH)               // 8 chunks
#define NROW (NB*HH)                 // 1792 global rows
#define QBLK 128                     // pixels per conv block
#define NQB  (NPIX/QBLK)             // 392

// ---------------- scratch (device globals) ---------------------------------
__device__ uint32_t g_bits[NPIX*CW];              // packed signs [q][8]
__device__ uint32_t g_wb[2][CC*72];               // packed weight signs
__device__ int      g_pw[2][CC*9];                // popcount of each weight tap
__device__ short    g_y[2][TOT];                  // integer conv outputs (NCHW)
__device__ int      g_pp1[CC*NQB], g_pp2[CC*NQB]; // per-(oc, qblock) partials
__device__ float    g_scale[2][CC], g_shift[2][CC];

// ---------------- pack weights: sign bits + per-tap popcounts -------------
__global__ void pack_w_kernel(const float* __restrict__ w1,
                              const float* __restrict__ w2) {
    int oc    = blockIdx.x;
    int which = blockIdx.y;
    const float* w = which ? w2 : w1;
    int tap  = threadIdx.y;          // 0..8
    int lane = threadIdx.x;          // 0..31
    int pwt = 0;
    #pragma unroll
    for (int j = 0; j < CW; j++) {
        float v = w[oc*2304 + (j*32 + lane)*9 + tap];
        unsigned word = __ballot_sync(0xffffffffu, v > 0.0f);
        if (lane == 0) g_wb[which][oc*72 + tap*8 + j] = word;
        pwt += __popc(word);
    }
    if (lane == 0) g_pw[which][oc*9 + tap] = pwt;
}

// ---------------- pack x signs (stage 1) ------------------------------------
__global__ void pack_sign_kernel(const float* __restrict__ src) {
    __shared__ unsigned char s[CC*WW];      // 7168 sign bytes
    int h = blockIdx.x, n = blockIdx.y;
    int basen = n * (CC*PIX);
    #pragma unroll
    for (int k = 0; k < 28; k++) {
        int e = threadIdx.x + k*256;         // e = c*28 + w
        int c = e / 28, w = e - c*28;
        float v = src[basen + c*PIX + h*WW + w];
        s[e] = (v > 0.0f) ? 1 : 0;
    }
    __syncthreads();
    int warp = threadIdx.x >> 5, lane = threadIdx.x & 31;
    #pragma unroll
    for (int w = 0; w < 28; w++) {
        unsigned pred = s[(warp*32 + lane)*28 + w];
        unsigned word = __ballot_sync(0xffffffffu, pred != 0);
        if (lane == w) g_bits[((n*HH + h)*WW + w)*CW + warp] = word;
    }
}

// ---------------- XNOR conv + fused BN-stat partials ------------------------
// Block = 128 consecutive pixels q x 32 ocs. ocs processed as 4 pairs-of-
// groups (8 ocs) with ky as middle loop -> A-tile LDS halved (72/warp).
// Epilogue: warp REDUX per oc -> smem -> per-(oc, qblock) partials (no atomics).
#define SMEM_W_U32  (OCCH*72)                 // 2304  [g][tap][o][j]
#define SMEM_A_U32  (9*2*32*4)                // 2304  [rowslot][half][col][k]
#define SMEM_ADJ    (OCCH*9)                  // 288
#define SMEM_U32    (SMEM_W_U32 + SMEM_A_U32 + SMEM_ADJ)

#define FA(x, y, z, s, c)  { s = (x)^(y)^(z); c = ((x)&(y)) | ((z)&((x)|(y))); }

__global__ void __launch_bounds__(128, 6) conv_kernel(int which) {
    extern __shared__ uint32_t sh[];
    uint32_t* s_w  = sh;                              // [g][tap][o][j0..7]
    uint32_t* s_a  = sh + SMEM_W_U32;                 // [slot][half][col][k]
    int*      s_adj = (int*)(sh + SMEM_W_U32 + SMEM_A_U32);
    __shared__ int s_p1[4][OCCH], s_p2[4][OCCH];

    const int q0  = blockIdx.x * QBLK;
    const int oc0 = blockIdx.y * OCCH;
    const int tid = threadIdx.x;
    const int R0  = q0 / 28;

    const uint32_t* wb = g_wb[which];
    for (int i = tid; i < SMEM_W_U32; i += 128) {
        int j   = i & 7;
        int o   = (i >> 3) & 3;
        int rem = i % 288;
        int tap = rem >> 5;
        int g   = i / 288;
        s_w[i] = wb[(oc0 + g*4 + o)*72 + tap*8 + j];
    }
    // activation tile: slots 0..7 = rows R0-1..R0+6, slot 8 = zeros
    for (int i = tid; i < SMEM_A_U32; i += 128) {
        uint32_t v = 0;
        if (i < 8*2*32*4) {
            int k    = i & 3;
            int col  = (i >> 2) & 31;
            int half = (i >> 7) & 1;
            int t    = i >> 8;
            int Rt   = R0 - 1 + t;
            int wo   = col - 1;
            if (Rt >= 0 && Rt < NROW && wo >= 0 && wo < 28)
                v = g_bits[(Rt*28 + wo)*CW + half*4 + k];
        }
        s_a[i] = v;
    }
    const int* pw = g_pw[which] + oc0*9;
    for (int e = tid; e < SMEM_ADJ; e += 128) {
        int ocl = e / 9, combo = e - ocl*9;
        int rs = combo / 3, cs = combo - rs*3;
        const int* pwo = pw + ocl*9;
        int corr = 0;
        if (rs) { int ir = (rs == 1) ? 0 : 2;
                  corr += pwo[ir*3] + pwo[ir*3+1] + pwo[ir*3+2]; }
        if (cs) { int ic = (cs == 1) ? 0 : 2;
                  corr += pwo[ic] + pwo[3+ic] + pwo[6+ic]; }
        if (rs && cs) { int ir = (rs == 1) ? 0 : 2, ic = (cs == 1) ? 0 : 2;
                        corr -= pwo[ir*3 + ic]; }
        int nv = (rs ? 2 : 3) * (cs ? 2 : 3);
        s_adj[e] = CC*nv + 2*corr;
    }
    __syncthreads();

    const int q = q0 + tid;             // all lanes active
    const int R = q / 28;
    const int w = q - R*28;
    const int h = R % 28;
    const int n = R / 28;
    const int pos = q - n*PIX;
    const int lane = tid & 31, wid = tid >> 5;

    const int rs = (h == 0) ? 1 : ((h == HH-1) ? 2 : 0);
    const int cs = (w == 0) ? 1 : ((w == WW-1) ? 2 : 0);
    const int combo = rs*3 + cs;

    const int bt = R - R0;              // 0..5
    const int t0 = (h > 0)    ? bt     : 8;   // ky=0 row slot
    const int t1 = bt + 1;                    // ky=1
    const int t2 = (h < HH-1) ? bt + 2 : 8;   // ky=2

    short* yout = g_y[which] + ((size_t)n*CC + oc0)*PIX + pos;  // + ocl*PIX

    for (int gp = 0; gp < 4; gp++) {           // pair of 4-oc groups = 8 ocs
        int a1[8], a2[8];
        #pragma unroll
        for (int o = 0; o < 8; o++) { a1[o] = 0; a2[o] = 0; }
        const uint4* wqA = (const uint4*)s_w + (gp*2)*72;
        #pragma unroll
        for (int ky = 0; ky < 3; ky++) {
            const int tk = (ky == 0) ? t0 : ((ky == 1) ? t1 : t2);
            const uint4* apL = (const uint4*)s_a + ((tk*2 + 0)*32 + w);
            const uint4* apH = (const uint4*)s_a + ((tk*2 + 1)*32 + w);
            uint4 L0 = apL[0], L1 = apL[1], L2 = apL[2];
            uint4 H0 = apH[0], H1 = apH[1], H2 = apH[2];
            #pragma unroll
            for (int kx = 0; kx < 3; kx++) {
                uint4 AL = (kx == 0) ? L0 : ((kx == 1) ? L1 : L2);
                uint4 AH = (kx == 0) ? H0 : ((kx == 1) ? H1 : H2);
                const uint4* wt = wqA + (ky*3 + kx)*8;
                #pragma unroll
                for (int gg = 0; gg < 2; gg++) {
                    const uint4* wg = wt + gg*72;
                    #pragma unroll
                    for (int o = 0; o < 4; o++) {
                        uint4 WL = wg[o*2], WH = wg[o*2 + 1];
                        uint32_t v0 = AL.x ^ WL.x, v1 = AL.y ^ WL.y;
                        uint32_t v2 = AL.z ^ WL.z, v3 = AL.w ^ WL.w;
                        uint32_t v4 = AH.x ^ WH.x, v5 = AH.y ^ WH.y;
                        uint32_t v6 = AH.z ^ WH.z, v7 = AH.w ^ WH.w;
                        uint32_t sA, cA, sB, cB, S, C;
                        FA(v0, v1, v2, sA, cA);
                        FA(v3, v4, v5, sB, cB);
                        FA(sA, sB, v6, S, C);
                        a1[gg*4 + o] += __popc(S) + __popc(v7);
                        a2[gg*4 + o] += __popc(cA) + __popc(cB) + __popc(C);
                    }
                }
            }
        }
        const int* adj = s_adj + (gp*8)*9 + combo;
        #pragma unroll
        for (int o = 0; o < 8; o++) {
            int y = adj[o*9] - 2*(a1[o] + 2*a2[o]);
            yout[(gp*8 + o)*PIX] = (short)y;
            int t1s = __reduce_add_sync(0xffffffffu, y);
            int t2s = __reduce_add_sync(0xffffffffu, y*y);  // <=32*2304^2 < 2^31
            if (lane == o) { s_p1[wid][gp*8 + o] = t1s; s_p2[wid][gp*8 + o] = t2s; }
        }
    }
    __syncthreads();
    if (tid < OCCH) {
        int v1 = s_p1[0][tid] + s_p1[1][tid] + s_p1[2][tid] + s_p1[3][tid];
        int v2 = s_p2[0][tid] + s_p2[1][tid] + s_p2[2][tid] + s_p2[3][tid];
        g_pp1[(oc0 + tid)*NQB + blockIdx.x] = v1;
        g_pp2[(oc0 + tid)*NQB + blockIdx.x] = v2;
    }
}

// ---------------- finalize BN coefficients from per-qblock partials --------
__global__ void __launch_bounds__(128) finalize_kernel(int which,
                                                       const float* __restrict__ gamma,
                                                       const float* __restrict__ beta) {
    const int oc = blockIdx.x;
    long long s1 = 0, s2 = 0;
    for (int i = threadIdx.x; i < NQB; i += 128) {   // coalesced [oc][qb]
        s1 += g_pp1[oc*NQB + i];
        s2 += g_pp2[oc*NQB + i];
    }
    #pragma unroll
    for (int o = 16; o; o >>= 1) {
        s1 += __shfl_down_sync(0xffffffffu, s1, o);
        s2 += __shfl_down_sync(0xffffffffu, s2, o);
    }
    __shared__ long long a1[4], a2[4];
    int wp = threadIdx.x >> 5, l = threadIdx.x & 31;
    if (l == 0) { a1[wp] = s1; a2[wp] = s2; }
    __syncthreads();
    if (threadIdx.x == 0) {
        long long t1 = a1[0]+a1[1]+a1[2]+a1[3], t2 = a2[0]+a2[1]+a2[2]+a2[3];
        double m   = (double)t1 / (double)NPIX;
        double ex2 = (double)t2 / (double)NPIX;
        double inv = rsqrt(ex2 - m*m + 1e-5);
        double gs  = (double)gamma[oc] * inv;
        g_scale[which][oc] = (float)gs;
        g_shift[which][oc] = (float)((double)beta[oc] - m * gs);
    }
}

// ---------------- stage-1 BN+res+clip -> stage-2 sign bits only ------------
__global__ void __launch_bounds__(256) bnres1_pack_kernel(const float* __restrict__ x) {
    __shared__ unsigned char s[CC*WW];
    __shared__ float ssc[CC], ssf[CC];
    int h = blockIdx.x, n = blockIdx.y, tid = threadIdx.x;
    ssc[tid] = g_scale[0][tid];
    ssf[tid] = g_shift[0][tid];
    __syncthreads();
    int basen = n * (CC*PIX);
    const short* yp = g_y[0];
    #pragma unroll
    for (int k = 0; k < 28; k++) {
        int e = tid + k*256;                 // e = c*28 + w
        int c = e / 28, w = e - c*28;
        int idx = basen + c*PIX + h*WW + w;
        float o = fmaf((float)yp[idx], ssc[c], ssf[c]) + x[idx];
        o = fminf(1.0f, fmaxf(-1.0f, o));
        s[e] = (o > 0.0f) ? 1 : 0;
    }
    __syncthreads();
    int warp = tid >> 5, lane = tid & 31;
    #pragma unroll
    for (int w = 0; w < 28; w++) {
        unsigned pred = s[(warp*32 + lane)*28 + w];
        unsigned word = __ballot_sync(0xffffffffu, pred != 0);
        if (lane == w) g_bits[((n*HH + h)*WW + w)*CW + warp] = word;
    }
}

// ---------------- stage-2: recompute o1, BN2 + res + clip (coalesced) ------
__global__ void __launch_bounds__(256) bnres2_kernel(const float* __restrict__ x,
                                                     float* __restrict__ dst_out) {
    int idx4 = blockIdx.x * 256 + threadIdx.x;     // grid = TOT/1024
    int base = idx4 << 2;
    int c = (base / PIX) & (CC - 1);
    float s0 = g_scale[0][c], f0 = g_shift[0][c];
    float s1 = g_scale[1][c], f1 = g_shift[1][c];
    short4 y1 = ((const short4*)g_y[0])[idx4];
    short4 y2 = ((const short4*)g_y[1])[idx4];
    float4 xv = ((const float4*)x)[idx4];
    float4 o;
    float o1;
    o1  = fminf(1.0f, fmaxf(-1.0f, fmaf((float)y1.x, s0, f0) + xv.x));
    o.x = fminf(1.0f, fmaxf(-1.0f, fmaf((float)y2.x, s1, f1) + o1));
    o1  = fminf(1.0f, fmaxf(-1.0f, fmaf((float)y1.y, s0, f0) + xv.y));
    o.y = fminf(1.0f, fmaxf(-1.0f, fmaf((float)y2.y, s1, f1) + o1));
    o1  = fminf(1.0f, fmaxf(-1.0f, fmaf((float)y1.z, s0, f0) + xv.z));
    o.z = fminf(1.0f, fmaxf(-1.0f, fmaf((float)y2.z, s1, f1) + o1));
    o1  = fminf(1.0f, fmaxf(-1.0f, fmaf((float)y1.w, s0, f0) + xv.w));
    o.w = fminf(1.0f, fmaxf(-1.0f, fmaf((float)y2.w, s1, f1) + o1));
    ((float4*)dst_out)[idx4] = o;
}

// ---------------- launcher -------------------------------------------------
extern "C" void kernel_launch(void* const* d_in, const int* in_sizes, int n_in,
                              void* d_out, int out_size) {
    const float* x      = (const float*)d_in[0];
    const float* w1     = (const float*)d_in[1];
    const float* gamma1 = (const float*)d_in[2];
    const float* beta1  = (const float*)d_in[3];
    const float* w2     = (const float*)d_in[4];
    const float* gamma2 = (const float*)d_in[5];
    const float* beta2  = (const float*)d_in[6];
    float* out = (float*)d_out;

    constexpr int SMEM_BYTES = SMEM_U32 * 4;       // 19,584 B dynamic

    pack_w_kernel<<<dim3(CC, 2), dim3(32, 9)>>>(w1, w2);

    // stage 1
    pack_sign_kernel<<<dim3(HH, NB), 256>>>(x);
    conv_kernel<<<dim3(NQB, NCH), 128, SMEM_BYTES>>>(0);
    finalize_kernel<<<CC, 128>>>(0, gamma1, beta1);
    bnres1_pack_kernel<<<dim3(HH, NB), 256>>>(x);   // stage-2 sign bits only

    // stage 2
    conv_kernel<<<dim3(NQB, NCH), 128, SMEM_BYTES>>>(1);
    finalize_kernel<<<CC, 128>>>(1, gamma2, beta2);
    bnres2_kernel<<<TOT/1024, 256>>>(x, out);
}

// round 16
// speedup vs baseline: 1.0299x; 1.0299x over previous
#include <cuda_runtime.h>
#include <cstdint>

// Problem constants
#define NB   64
#define CC   256
#define HH   28
#define WW   28
#define PIX  (HH*WW)                 // 784
#define NPIX (NB*PIX)                // 50176
#define TOT  (NB*CC*PIX)             // 12,845,056
#define CW   8                       // 256 channels / 32 bits
#define OCCH 32                      // output channels per block
#define NCH  (CC/OCCH)               // 8 chunks
#define NG   (OCCH/4)                // 8 groups of 4 ocs
#define NROW (NB*HH)                 // 1792 global rows
#define QBLK 128                     // pixels per conv block
#define NQB  (NPIX/QBLK)             // 392

// ---------------- scratch (device globals) ---------------------------------
__device__ uint32_t g_bits[NPIX*CW];              // packed signs [q][8]
__device__ uint32_t g_wb[2][CC*72];               // packed weight signs
__device__ int      g_pw[2][CC*9];                // popcount of each weight tap
__device__ short    g_y[2][TOT];                  // integer conv outputs (NCHW)
__device__ int      g_pp1[CC*NQB], g_pp2[CC*NQB]; // per-(oc, qblock) partials
__device__ float    g_scale[2][CC], g_shift[2][CC];

// ---------------- pack weights: sign bits + per-tap popcounts -------------
__global__ void pack_w_kernel(const float* __restrict__ w1,
                              const float* __restrict__ w2) {
    int oc    = blockIdx.x;
    int which = blockIdx.y;
    const float* w = which ? w2 : w1;
    int tap  = threadIdx.y;          // 0..8
    int lane = threadIdx.x;          // 0..31
    int pwt = 0;
    #pragma unroll
    for (int j = 0; j < CW; j++) {
        float v = w[oc*2304 + (j*32 + lane)*9 + tap];
        unsigned word = __ballot_sync(0xffffffffu, v > 0.0f);
        if (lane == 0) g_wb[which][oc*72 + tap*8 + j] = word;
        pwt += __popc(word);
    }
    if (lane == 0) g_pw[which][oc*9 + tap] = pwt;
}

// ---------------- pack x signs (stage 1) ------------------------------------
__global__ void pack_sign_kernel(const float* __restrict__ src) {
    __shared__ unsigned char s[CC*WW];      // 7168 sign bytes
    int h = blockIdx.x, n = blockIdx.y;
    int basen = n * (CC*PIX);
    #pragma unroll
    for (int k = 0; k < 28; k++) {
        int e = threadIdx.x + k*256;         // e = c*28 + w
        int c = e / 28, w = e - c*28;
        float v = src[basen + c*PIX + h*WW + w];
        s[e] = (v > 0.0f) ? 1 : 0;
    }
    __syncthreads();
    int warp = threadIdx.x >> 5, lane = threadIdx.x & 31;
    #pragma unroll
    for (int w = 0; w < 28; w++) {
        unsigned pred = s[(warp*32 + lane)*28 + w];
        unsigned word = __ballot_sync(0xffffffffu, pred != 0);
        if (lane == w) g_bits[((n*HH + h)*WW + w)*CW + warp] = word;
    }
}

// ---------------- XNOR conv (R14 inner loop) + fused stat partials ---------
// Block = 128 consecutive pixels q x 32 ocs, 4-oc groups (R14-proven).
// Epilogue per oc: warp REDUX -> smem -> per-(oc, qblock) partials.
#define SMEM_W_U32  (OCCH*72)                 // 2304  [g][tap][o][j]
#define SMEM_A_U32  (9*2*32*4)                // 2304  [rowslot][half][col][k]
#define SMEM_ADJ    (OCCH*9)                  // 288
#define SMEM_U32    (SMEM_W_U32 + SMEM_A_U32 + SMEM_ADJ)

#define FA(x, y, z, s, c)  { s = (x)^(y)^(z); c = ((x)&(y)) | ((z)&((x)|(y))); }

__global__ void __launch_bounds__(128, 6) conv_kernel(int which) {
    extern __shared__ uint32_t sh[];
    uint32_t* s_w  = sh;                              // [g][tap][o][j0..7]
    uint32_t* s_a  = sh + SMEM_W_U32;                 // [slot][half][col][k]
    int*      s_adj = (int*)(sh + SMEM_W_U32 + SMEM_A_U32);
    __shared__ int s_p1[4][OCCH], s_p2[4][OCCH];

    const int q0  = blockIdx.x * QBLK;
    const int oc0 = blockIdx.y * OCCH;
    const int tid = threadIdx.x;
    const int R0  = q0 / 28;

    const uint32_t* wb = g_wb[which];
    for (int i = tid; i < SMEM_W_U32; i += 128) {
        int j   = i & 7;
        int o   = (i >> 3) & 3;
        int rem = i % 288;
        int tap = rem >> 5;
        int g   = i / 288;
        s_w[i] = wb[(oc0 + g*4 + o)*72 + tap*8 + j];
    }
    // activation tile: slots 0..7 = rows R0-1..R0+6, slot 8 = zeros
    for (int i = tid; i < SMEM_A_U32; i += 128) {
        uint32_t v = 0;
        if (i < 8*2*32*4) {
            int k    = i & 3;
            int col  = (i >> 2) & 31;
            int half = (i >> 7) & 1;
            int t    = i >> 8;
            int Rt   = R0 - 1 + t;
            int wo   = col - 1;
            if (Rt >= 0 && Rt < NROW && wo >= 0 && wo < 28)
                v = g_bits[(Rt*28 + wo)*CW + half*4 + k];
        }
        s_a[i] = v;
    }
    const int* pw = g_pw[which] + oc0*9;
    for (int e = tid; e < SMEM_ADJ; e += 128) {
        int ocl = e / 9, combo = e - ocl*9;
        int rs = combo / 3, cs = combo - rs*3;
        const int* pwo = pw + ocl*9;
        int corr = 0;
        if (rs) { int ir = (rs == 1) ? 0 : 2;
                  corr += pwo[ir*3] + pwo[ir*3+1] + pwo[ir*3+2]; }
        if (cs) { int ic = (cs == 1) ? 0 : 2;
                  corr += pwo[ic] + pwo[3+ic] + pwo[6+ic]; }
        if (rs && cs) { int ir = (rs == 1) ? 0 : 2, ic = (cs == 1) ? 0 : 2;
                        corr -= pwo[ir*3 + ic]; }
        int nv = (rs ? 2 : 3) * (cs ? 2 : 3);
        s_adj[e] = CC*nv + 2*corr;
    }
    __syncthreads();

    const int q = q0 + tid;             // all lanes active
    const int R = q / 28;
    const int w = q - R*28;
    const int h = R % 28;
    const int n = R / 28;
    const int pos = q - n*PIX;
    const int lane = tid & 31, wid = tid >> 5;

    const int rs = (h == 0) ? 1 : ((h == HH-1) ? 2 : 0);
    const int cs = (w == 0) ? 1 : ((w == WW-1) ? 2 : 0);
    const int combo = rs*3 + cs;

    const int bt = R - R0;              // 0..5
    const int t0 = (h > 0)    ? bt     : 8;   // ky=0 row slot
    const int t1 = bt + 1;                    // ky=1
    const int t2 = (h < HH-1) ? bt + 2 : 8;   // ky=2

    short* yout = g_y[which] + ((size_t)n*CC + oc0)*PIX + pos;  // + ocl*PIX

    for (int g = 0; g < NG; g++) {
        int acc1_0 = 0, acc1_1 = 0, acc1_2 = 0, acc1_3 = 0;   // weight-1 popcs
        int acc2_0 = 0, acc2_1 = 0, acc2_2 = 0, acc2_3 = 0;   // weight-2 popcs
        const uint4* wq = (const uint4*)s_w + g*72;            // [tap][o][lo/hi]
        #pragma unroll
        for (int ky = 0; ky < 3; ky++) {
            const int tk = (ky == 0) ? t0 : ((ky == 1) ? t1 : t2);
            const uint4* apL = (const uint4*)s_a + ((tk*2 + 0)*32 + w);
            const uint4* apH = (const uint4*)s_a + ((tk*2 + 1)*32 + w);
            uint4 L0 = apL[0], L1 = apL[1], L2 = apL[2];
            uint4 H0 = apH[0], H1 = apH[1], H2 = apH[2];
            #pragma unroll
            for (int kx = 0; kx < 3; kx++) {
                uint4 AL = (kx == 0) ? L0 : ((kx == 1) ? L1 : L2);
                uint4 AH = (kx == 0) ? H0 : ((kx == 1) ? H1 : H2);
                const uint4* wt = wq + (ky*3 + kx)*8;
                #pragma unroll
                for (int o = 0; o < 4; o++) {
                    uint4 WL = wt[o*2], WH = wt[o*2 + 1];
                    uint32_t v0 = AL.x ^ WL.x, v1 = AL.y ^ WL.y;
                    uint32_t v2 = AL.z ^ WL.z, v3 = AL.w ^ WL.w;
                    uint32_t v4 = AH.x ^ WH.x, v5 = AH.y ^ WH.y;
                    uint32_t v6 = AH.z ^ WH.z, v7 = AH.w ^ WH.w;
                    uint32_t sA, cA, sB, cB, S, C;
                    FA(v0, v1, v2, sA, cA);
                    FA(v3, v4, v5, sB, cB);
                    FA(sA, sB, v6, S, C);
                    int p1 = __popc(S) + __popc(v7);
                    int p2 = __popc(cA) + __popc(cB) + __popc(C);
                    if (o == 0) { acc1_0 += p1; acc2_0 += p2; }
                    if (o == 1) { acc1_1 += p1; acc2_1 += p2; }
                    if (o == 2) { acc1_2 += p1; acc2_2 += p2; }
                    if (o == 3) { acc1_3 += p1; acc2_3 += p2; }
                }
            }
        }
        const int* adj = s_adj + (g*4)*9 + combo;
        int y0 = adj[0]  - 2*(acc1_0 + 2*acc2_0);
        int y1 = adj[9]  - 2*(acc1_1 + 2*acc2_1);
        int y2 = adj[18] - 2*(acc1_2 + 2*acc2_2);
        int y3 = adj[27] - 2*(acc1_3 + 2*acc2_3);
        yout[(g*4 + 0)*PIX] = (short)y0;
        yout[(g*4 + 1)*PIX] = (short)y1;
        yout[(g*4 + 2)*PIX] = (short)y2;
        yout[(g*4 + 3)*PIX] = (short)y3;
        // fused BN-stat partials: warp REDUX per oc (y^2 <= 32*2304^2 < 2^31)
        int t1s, t2s;
        t1s = __reduce_add_sync(0xffffffffu, y0);
        t2s = __reduce_add_sync(0xffffffffu, y0*y0);
        if (lane == 0) { s_p1[wid][g*4 + 0] = t1s; s_p2[wid][g*4 + 0] = t2s; }
        t1s = __reduce_add_sync(0xffffffffu, y1);
        t2s = __reduce_add_sync(0xffffffffu, y1*y1);
        if (lane == 1) { s_p1[wid][g*4 + 1] = t1s; s_p2[wid][g*4 + 1] = t2s; }
        t1s = __reduce_add_sync(0xffffffffu, y2);
        t2s = __reduce_add_sync(0xffffffffu, y2*y2);
        if (lane == 2) { s_p1[wid][g*4 + 2] = t1s; s_p2[wid][g*4 + 2] = t2s; }
        t1s = __reduce_add_sync(0xffffffffu, y3);
        t2s = __reduce_add_sync(0xffffffffu, y3*y3);
        if (lane == 3) { s_p1[wid][g*4 + 3] = t1s; s_p2[wid][g*4 + 3] = t2s; }
    }
    __syncthreads();
    if (tid < OCCH) {
        int v1 = s_p1[0][tid] + s_p1[1][tid] + s_p1[2][tid] + s_p1[3][tid];
        int v2 = s_p2[0][tid] + s_p2[1][tid] + s_p2[2][tid] + s_p2[3][tid];
        g_pp1[(oc0 + tid)*NQB + blockIdx.x] = v1;
        g_pp2[(oc0 + tid)*NQB + blockIdx.x] = v2;
    }
}

// ---------------- finalize BN coefficients from per-qblock partials --------
__global__ void __launch_bounds__(128) finalize_kernel(int which,
                                                       const float* __restrict__ gamma,
                                                       const float* __restrict__ beta) {
    const int oc = blockIdx.x;
    long long s1 = 0, s2 = 0;
    for (int i = threadIdx.x; i < NQB; i += 128) {   // coalesced [oc][qb]
        s1 += g_pp1[oc*NQB + i];
        s2 += g_pp2[oc*NQB + i];
    }
    #pragma unroll
    for (int o = 16; o; o >>= 1) {
        s1 += __shfl_down_sync(0xffffffffu, s1, o);
        s2 += __shfl_down_sync(0xffffffffu, s2, o);
    }
    __shared__ long long a1[4], a2[4];
    int wp = threadIdx.x >> 5, l = threadIdx.x & 31;
    if (l == 0) { a1[wp] = s1; a2[wp] = s2; }
    __syncthreads();
    if (threadIdx.x == 0) {
        long long t1 = a1[0]+a1[1]+a1[2]+a1[3], t2 = a2[0]+a2[1]+a2[2]+a2[3];
        double m   = (double)t1 / (double)NPIX;
        double ex2 = (double)t2 / (double)NPIX;
        double inv = rsqrt(ex2 - m*m + 1e-5);
        double gs  = (double)gamma[oc] * inv;
        g_scale[which][oc] = (float)gs;
        g_shift[which][oc] = (float)((double)beta[oc] - m * gs);
    }
}

// ---------------- stage-1 BN+res+clip -> stage-2 sign bits only ------------
__global__ void __launch_bounds__(256) bnres1_pack_kernel(const float* __restrict__ x) {
    __shared__ unsigned char s[CC*WW];
    __shared__ float ssc[CC], ssf[CC];
    int h = blockIdx.x, n = blockIdx.y, tid = threadIdx.x;
    ssc[tid] = g_scale[0][tid];
    ssf[tid] = g_shift[0][tid];
    __syncthreads();
    int basen = n * (CC*PIX);
    const short* yp = g_y[0];
    #pragma unroll
    for (int k = 0; k < 28; k++) {
        int e = tid + k*256;                 // e = c*28 + w
        int c = e / 28, w = e - c*28;
        int idx = basen + c*PIX + h*WW + w;
        float o = fmaf((float)yp[idx], ssc[c], ssf[c]) + x[idx];
        o = fminf(1.0f, fmaxf(-1.0f, o));
        s[e] = (o > 0.0f) ? 1 : 0;
    }
    __syncthreads();
    int warp = tid >> 5, lane = tid & 31;
    #pragma unroll
    for (int w = 0; w < 28; w++) {
        unsigned pred = s[(warp*32 + lane)*28 + w];
        unsigned word = __ballot_sync(0xffffffffu, pred != 0);
        if (lane == w) g_bits[((n*HH + h)*WW + w)*CW + warp] = word;
    }
}

// ---------------- stage-2: recompute o1, BN2 + res + clip (coalesced) ------
__global__ void __launch_bounds__(256) bnres2_kernel(const float* __restrict__ x,
                                                     float* __restrict__ dst_out) {
    int idx4 = blockIdx.x * 256 + threadIdx.x;     // grid = TOT/1024
    int base = idx4 << 2;
    int c = (base / PIX) & (CC - 1);
    float s0 = g_scale[0][c], f0 = g_shift[0][c];
    float s1 = g_scale[1][c], f1 = g_shift[1][c];
    short4 y1 = ((const short4*)g_y[0])[idx4];
    short4 y2 = ((const short4*)g_y[1])[idx4];
    float4 xv = ((const float4*)x)[idx4];
    float4 o;
    float o1;
    o1  = fminf(1.0f, fmaxf(-1.0f, fmaf((float)y1.x, s0, f0) + xv.x));
    o.x = fminf(1.0f, fmaxf(-1.0f, fmaf((float)y2.x, s1, f1) + o1));
    o1  = fminf(1.0f, fmaxf(-1.0f, fmaf((float)y1.y, s0, f0) + xv.y));
    o.y = fminf(1.0f, fmaxf(-1.0f, fmaf((float)y2.y, s1, f1) + o1));
    o1  = fminf(1.0f, fmaxf(-1.0f, fmaf((float)y1.z, s0, f0) + xv.z));
    o.z = fminf(1.0f, fmaxf(-1.0f, fmaf((float)y2.z, s1, f1) + o1));
    o1  = fminf(1.0f, fmaxf(-1.0f, fmaf((float)y1.w, s0, f0) + xv.w));
    o.w = fminf(1.0f, fmaxf(-1.0f, fmaf((float)y2.w, s1, f1) + o1));
    ((float4*)dst_out)[idx4] = o;
}

// ---------------- launcher -------------------------------------------------
extern "C" void kernel_launch(void* const* d_in, const int* in_sizes, int n_in,
                              void* d_out, int out_size) {
    const float* x      = (const float*)d_in[0];
    const float* w1     = (const float*)d_in[1];
    const float* gamma1 = (const float*)d_in[2];
    const float* beta1  = (const float*)d_in[3];
    const float* w2     = (const float*)d_in[4];
    const float* gamma2 = (const float*)d_in[5];
    const float* beta2  = (const float*)d_in[6];
    float* out = (float*)d_out;

    constexpr int SMEM_BYTES = SMEM_U32 * 4;       // 19,584 B dynamic

    pack_w_kernel<<<dim3(CC, 2), dim3(32, 9)>>>(w1, w2);

    // stage 1
    pack_sign_kernel<<<dim3(HH, NB), 256>>>(x);
    conv_kernel<<<dim3(NQB, NCH), 128, SMEM_BYTES>>>(0);
    finalize_kernel<<<CC, 128>>>(0, gamma1, beta1);
    bnres1_pack_kernel<<<dim3(HH, NB), 256>>>(x);   // stage-2 sign bits only

    // stage 2
    conv_kernel<<<dim3(NQB, NCH), 128, SMEM_BYTES>>>(1);
    finalize_kernel<<<CC, 128>>>(1, gamma2, beta2);
    bnres2_kernel<<<TOT/1024, 256>>>(x, out);
}